// round 1
// baseline (speedup 1.0000x reference)
#include <cuda_runtime.h>
#include <cuda_bf16.h>

// Problem constants (fixed shapes from reference)
#define Bn 512
#define Tn 512
#define Cn 128
#define Ln 32
#define Sn 65            // 2*L + 1
#define BLANKC 127       // last class is blank
#define EPSF 1e-7f
#define NEGF -1e30f

// log(exp(a) + exp(b)) in a numerically safe, -1e30-tolerant way.
// m = max, d = min - max <= 0; __expf(d) in (0,1], __logf(1+x) on [1,2] is
// accurate to ~1e-7 absolute, fine for 1e-3 rel tolerance over 512 steps.
__device__ __forceinline__ float lae(float a, float b) {
    float m = fmaxf(a, b);
    float d = fminf(a, b) - m;
    return m + __logf(1.0f + __expf(d));
}

__global__ __launch_bounds__(128, 8)
void CTCLayer_kernel(const int* __restrict__ y_true,
                     const float* __restrict__ y_pred,
                     float* __restrict__ out) {
    // Shared state: double-buffered prob row + double-buffered alpha (padded
    // by 2 NEG entries so s-1 / s-2 accesses are branch-free).
    __shared__ float rowbuf[2][Cn];
    __shared__ float abuf[2][Sn + 2];
    __shared__ int   ext[Sn];
    __shared__ unsigned char skip[Sn];

    const int b   = blockIdx.x;
    const int tid = threadIdx.x;
    const float* __restrict__ base = y_pred + (size_t)b * Tn * Cn;

    // --- one-time setup -----------------------------------------------------
    if (tid < Sn) {
        int e = (tid & 1) ? y_true[b * Ln + (tid >> 1)] : BLANKC;
        ext[tid] = e;
    }
    if (tid < 2) {
        abuf[0][tid] = NEGF;  // permanent NEG pads at indices 0,1
        abuf[1][tid] = NEGF;
    }
    if (tid < Cn) rowbuf[0][tid] = base[tid];   // row t=0, coalesced
    __syncthreads();

    if (tid < Sn) {
        unsigned char sk = 0;
        if (tid >= 2) {
            int e = ext[tid];
            sk = (e != BLANKC && e != ext[tid - 2]) ? 1 : 0;
        }
        skip[tid] = sk;   // consumed first at t=1; a barrier intervenes (t=0 loop end)
    }

    // --- forward scan -------------------------------------------------------
    int cur = 0;
    #pragma unroll 1
    for (int t = 0; t < Tn; ++t) {
        // Software-pipelined prefetch of next row (LDG issued before the
        // compute chain; STS happens just before the barrier).
        float pre = 0.0f;
        const bool has_next = (t + 1 < Tn);
        if (has_next && tid < Cn) pre = base[(size_t)(t + 1) * Cn + tid];

        float an = NEGF;
        if (tid < Sn) {
            float lp = __logf(rowbuf[cur][ext[tid]] + EPSF);
            if (t == 0) {
                an = (tid < 2) ? lp : NEGF;
            } else {
                float a0 = abuf[cur][tid + 2];
                float a1 = abuf[cur][tid + 1];
                float a2 = skip[tid] ? abuf[cur][tid] : NEGF;
                an = lae(lae(a0, a1), a2) + lp;
            }
        }
        // Double buffering: reads hit buffer `cur`, writes hit `cur^1`, so a
        // single barrier per step suffices (separates this step's reads from
        // next step's writes back into `cur`).
        if (tid < Sn) abuf[cur ^ 1][tid + 2] = an;
        if (has_next && tid < Cn) rowbuf[cur ^ 1][tid] = pre;
        __syncthreads();
        cur ^= 1;
    }

    // loss = -logaddexp(alpha[S-1], alpha[S-2])
    if (tid == 0) {
        out[b] = -lae(abuf[cur][Sn - 1 + 2], abuf[cur][Sn - 2 + 2]);
    }
}

extern "C" void kernel_launch(void* const* d_in, const int* in_sizes, int n_in,
                              void* d_out, int out_size) {
    // Resolve input order defensively by element count:
    // y_true: B*L = 16384 int32 ; y_pred: B*T*C = 33554432 float32
    int it = 0, ip = 1;
    if (n_in >= 2 && in_sizes[0] != Bn * Ln) { it = 1; ip = 0; }
    const int*   y_true = (const int*)d_in[it];
    const float* y_pred = (const float*)d_in[ip];
    float*       out    = (float*)d_out;
    (void)out_size;

    CTCLayer_kernel<<<Bn, 128>>>(y_true, y_pred, out);
}

// round 6
// speedup vs baseline: 3.0481x; 3.0481x over previous
#include <cuda_runtime.h>
#include <cuda_bf16.h>

// Problem constants (fixed shapes from reference)
#define Bn 512
#define Tn 512
#define Cn 128
#define Ln 32
#define BLANKC 127       // last class is blank
#define EPSF 1e-7f
#define NEGF -1e30f
#define FULLM 0xffffffffu
#define PCH 8            // prefetch depth (timesteps)
#define WPB 4            // warps (batches) per block -> one warp per SMSP

// fast logaddexp; NEG-safe: __expf(-1e30)=0, __logf(1)=0.
__device__ __forceinline__ float lae(float a, float b) {
    float m = fmaxf(a, b);
    float d = fminf(a, b) - m;
    return m + __logf(1.0f + __expf(d));
}

// Warp-per-batch CTC forward in LOG domain (numerically unconditional).
// Lane i owns alpha[2i] (blank, aL) and alpha[2i+1] (label i, aH); lane 31
// also owns alpha[64] (aE) -- its update lae(aE,aH)+lpB is lane-local.
// Per step: ONE shfl_up (alpha[2i-1]) + three logaddexps; no barriers.
// 4 warps/block so each warp gets a private SMSP (MUFU-throughput co-binding).
__global__ __launch_bounds__(WPB * 32, 8)
void CTCLayer_kernel(const int* __restrict__ y_true,
                     const float* __restrict__ y_pred,
                     float* __restrict__ out) {
    const int lane = threadIdx.x & 31;
    const int b    = blockIdx.x * WPB + (threadIdx.x >> 5);
    const float* __restrict__ row0 = y_pred + (size_t)b * Tn * Cn;

    // Odd state 2i+1 skip: i>0 and label[i] != label[i-1] (labels never BLANK).
    const int lab     = y_true[b * Ln + lane];
    const int labPrev = __shfl_up_sync(FULLM, lab, 1);
    const bool skip   = (lane > 0 && lab != labPrev);

    // ---- prefetch chunk 0 --------------------------------------------------
    float curL[PCH], curB[PCH], nxtL[PCH], nxtB[PCH];
    #pragma unroll
    for (int j = 0; j < PCH; ++j) {
        curL[j] = __ldcs(row0 + j * Cn + lab);     // scattered, touched once
        curB[j] = __ldg (row0 + j * Cn + BLANKC);  // warp-broadcast sector
    }

    // t = 0 init: alpha[0]=lpB, alpha[1]=lpL on lane 0; others NEG.
    float aL = (lane == 0) ? __logf(curB[0] + EPSF) : NEGF;
    float aH = (lane == 0) ? __logf(curL[0] + EPSF) : NEGF;
    float aE = NEGF;

    #pragma unroll 1
    for (int c = 0; c < Tn / PCH; ++c) {
        if (c + 1 < Tn / PCH) {
            const float* rw = row0 + (size_t)(c + 1) * PCH * Cn;
            #pragma unroll
            for (int j = 0; j < PCH; ++j) {
                nxtL[j] = __ldcs(rw + j * Cn + lab);
                nxtB[j] = __ldg (rw + j * Cn + BLANKC);
            }
        }
        const int j0 = (c == 0) ? 1 : 0;   // chunk 0: t=0 consumed by init
        #pragma unroll
        for (int j = 0; j < PCH; ++j) {
            if (j < j0) continue;
            float lpL = __logf(curL[j] + EPSF);    // off critical path
            float lpB = __logf(curB[j] + EPSF);

            float ph = __shfl_up_sync(FULLM, aH, 1);   // alpha[2i-1]
            if (lane == 0) ph = NEGF;

            // even state 2i: from {2i, 2i-1}
            float nL = lae(aL, ph) + lpB;
            // tail state 64 (lane 31 only; garbage elsewhere is harmless)
            float nE = lae(aE, aH) + lpB;
            // odd state 2i+1: from {2i+1, 2i, [2i-1]} -- 3-way, parallel exps
            float cc = skip ? ph : NEGF;
            float m3 = fmaxf(fmaxf(aH, aL), cc);
            float s3 = __expf(aH - m3) + __expf(aL - m3) + __expf(cc - m3);
            float nH = m3 + __logf(s3) + lpL;

            aL = nL; aH = nH; aE = nE;
        }
        #pragma unroll
        for (int j = 0; j < PCH; ++j) { curL[j] = nxtL[j]; curB[j] = nxtB[j]; }
    }

    // loss = -logaddexp(alpha[64], alpha[63])
    if (lane == 31) {
        out[b] = -lae(aE, aH);
    }
}

extern "C" void kernel_launch(void* const* d_in, const int* in_sizes, int n_in,
                              void* d_out, int out_size) {
    // Resolve input order defensively by element count:
    // y_true: B*L = 16384 int32 ; y_pred: B*T*C = 33554432 float32
    int it = 0, ip = 1;
    if (n_in >= 2 && in_sizes[0] != Bn * Ln) { it = 1; ip = 0; }
    const int*   y_true = (const int*)d_in[it];
    const float* y_pred = (const float*)d_in[ip];
    float*       out    = (float*)d_out;
    (void)out_size;

    CTCLayer_kernel<<<Bn / WPB, WPB * 32>>>(y_true, y_pred, out);
}